// round 1
// baseline (speedup 1.0000x reference)
#include <cuda_runtime.h>
#include <cuda_bf16.h>

// Problem constants
#define B_   8
#define LQ_  2048
#define LK_  2048
#define DQ_  1024
#define DKEY_ 1024
#define DV_  1024

// Scratch (allocation-free rule: __device__ globals)
__device__ float g_Qp[(long long)B_ * LQ_ * DKEY_];   // 64 MB: projected Q
__device__ float g_S [(long long)B_ * LQ_ * LK_];     // 134 MB: scores / probs

// ---------------------------------------------------------------------------
// Tiled SGEMM: C = alpha * A @ B(^T), batched via blockIdx.z.
// BM=BN=128, BK=8, 256 threads, 8x8 microtile per thread.
// TRANSB:  B is [N,K] row-major (C = A @ B^T)   else B is [K,N] row-major.
// SKIPN:   skip whole N-tiles at/above lens[b]  (QK^T masked region).
// KBOUND:  clip K loop to round_up(lens[b], BK) (PV: P rows >= L are zero).
// All dims here are multiples of the tile sizes (1024/2048/16384) -> no edge code.
// ---------------------------------------------------------------------------
constexpr int BM = 128, BN = 128, BK = 8, TM = 8, TN = 8;

template<bool TRANSB, bool SKIPN, bool KBOUND>
__global__ __launch_bounds__(256)
void sgemm_kernel(const float* __restrict__ A, const float* __restrict__ B,
                  float* __restrict__ C,
                  int M, int N, int K,
                  long long sA, long long sB, long long sC,
                  float alpha, const int* __restrict__ lens)
{
    const int b = blockIdx.z;
    int L = 0;
    if (SKIPN || KBOUND) L = lens[b];
    if (SKIPN) {
        if ((int)blockIdx.x * BN >= L) return;   // fully-masked score tile
    }
    int Keff = K;
    if (KBOUND) {
        int r = ((L + BK - 1) / BK) * BK;
        Keff = r < K ? r : K;
    }

    A += (long long)b * sA;
    B += (long long)b * sB;
    C += (long long)b * sC;

    const int lda = K;
    const int ldb = TRANSB ? K : N;

    __shared__ float As[BK][BM];
    __shared__ float Bs[BK][BN];

    const int tid  = threadIdx.x;
    const int tRow = tid / (BN / TN);   // 0..15
    const int tCol = tid % (BN / TN);   // 0..15

    // A loader: 128x8 tile, one float4 per thread along K, stored transposed.
    const int aRow = tid >> 1;          // 0..127
    const int aCol = (tid & 1) * 4;     // 0 or 4

    float acc[TM][TN];
#pragma unroll
    for (int i = 0; i < TM; i++)
#pragma unroll
        for (int j = 0; j < TN; j++) acc[i][j] = 0.f;

    const float* Aptr = A + ((long long)(blockIdx.y * BM + aRow)) * lda + aCol;
    const float* Bptr;
    if (TRANSB) {
        // need Bs[k][n] = B[(n0+n)*K + kt+k]; one float4 per thread along K
        Bptr = B + ((long long)(blockIdx.x * BN + (tid >> 1))) * (long long)ldb + (tid & 1) * 4;
    } else {
        // 8x128 tile, one float4 per thread along N
        Bptr = B + ((long long)(tid >> 5)) * (long long)ldb + blockIdx.x * BN + (tid & 31) * 4;
    }

    for (int kt = 0; kt < Keff; kt += BK) {
        float4 av = *(const float4*)Aptr;
        As[aCol + 0][aRow] = av.x;
        As[aCol + 1][aRow] = av.y;
        As[aCol + 2][aRow] = av.z;
        As[aCol + 3][aRow] = av.w;

        float4 bv = *(const float4*)Bptr;
        if (TRANSB) {
            const int n  = tid >> 1;
            const int k4 = (tid & 1) * 4;
            Bs[k4 + 0][n] = bv.x;
            Bs[k4 + 1][n] = bv.y;
            Bs[k4 + 2][n] = bv.z;
            Bs[k4 + 3][n] = bv.w;
        } else {
            *(float4*)&Bs[tid >> 5][(tid & 31) * 4] = bv;
        }
        __syncthreads();

        Aptr += BK;
        Bptr += TRANSB ? (long long)BK : (long long)BK * ldb;

#pragma unroll
        for (int k = 0; k < BK; k++) {
            float regM[TM], regN[TN];
#pragma unroll
            for (int i = 0; i < TM; i++) regM[i] = As[k][tRow * TM + i];
#pragma unroll
            for (int j = 0; j < TN; j++) regN[j] = Bs[k][tCol * TN + j];
#pragma unroll
            for (int i = 0; i < TM; i++)
#pragma unroll
                for (int j = 0; j < TN; j++)
                    acc[i][j] += regM[i] * regN[j];
        }
        __syncthreads();
    }

#pragma unroll
    for (int i = 0; i < TM; i++) {
        long long crow = (long long)(blockIdx.y * BM + tRow * TM + i);
        float4* cptr = (float4*)(C + crow * (long long)N + blockIdx.x * BN + tCol * TN);
        float4 v0, v1;
        v0.x = alpha * acc[i][0]; v0.y = alpha * acc[i][1];
        v0.z = alpha * acc[i][2]; v0.w = alpha * acc[i][3];
        v1.x = alpha * acc[i][4]; v1.y = alpha * acc[i][5];
        v1.z = alpha * acc[i][6]; v1.w = alpha * acc[i][7];
        cptr[0] = v0; cptr[1] = v1;
    }
}

// ---------------------------------------------------------------------------
// Masked softmax over rows of S[b][q][0..LK). Positions >= lens[b] become 0
// (identical to exp(-1e6 - m) == 0 in fp32). One block per row, 256 threads,
// 8 elements/thread kept in registers.
// ---------------------------------------------------------------------------
__global__ __launch_bounds__(256)
void softmax_mask_kernel(float* __restrict__ S, const int* __restrict__ lens)
{
    const int row = blockIdx.x;            // b*LQ + q
    const int b   = row / LQ_;
    const int L   = lens[b];
    float* Srow = S + (long long)row * LK_;

    const int tid = threadIdx.x;
    float v[8];
    float m = -3.4e38f;
#pragma unroll
    for (int i = 0; i < 8; i++) {
        const int s = tid + i * 256;
        v[i] = Srow[s];
        if (s < L) m = fmaxf(m, v[i]);
    }

    __shared__ float sdata[256];
    sdata[tid] = m;
    __syncthreads();
    for (int stride = 128; stride > 0; stride >>= 1) {
        if (tid < stride) sdata[tid] = fmaxf(sdata[tid], sdata[tid + stride]);
        __syncthreads();
    }
    m = sdata[0];
    __syncthreads();

    float sum = 0.f;
#pragma unroll
    for (int i = 0; i < 8; i++) {
        const int s = tid + i * 256;
        v[i] = (s < L) ? expf(v[i] - m) : 0.f;
        sum += v[i];
    }
    sdata[tid] = sum;
    __syncthreads();
    for (int stride = 128; stride > 0; stride >>= 1) {
        if (tid < stride) sdata[tid] += sdata[tid + stride];
        __syncthreads();
    }
    const float inv = 1.f / sdata[0];

#pragma unroll
    for (int i = 0; i < 8; i++)
        Srow[tid + i * 256] = v[i] * inv;
}

// ---------------------------------------------------------------------------
// Launch: Qp = queries @ W_q ; S = Qp @ K^T / 32 (skip masked tiles) ;
//         P = masked_softmax(S) ; out = P @ V (K-loop clipped at valid_len).
// ---------------------------------------------------------------------------
extern "C" void kernel_launch(void* const* d_in, const int* in_sizes, int n_in,
                              void* d_out, int out_size)
{
    const float* queries = (const float*)d_in[0];   // [8,2048,1024]
    const float* keys    = (const float*)d_in[1];   // [8,2048,1024]
    const float* values  = (const float*)d_in[2];   // [8,2048,1024]
    const int*   lens    = (const int*)  d_in[3];   // [8]
    const float* Wq      = (const float*)d_in[4];   // [1024,1024]
    float*       out     = (float*)d_out;           // [8,2048,1024]

    void* pQp = nullptr;
    void* pS  = nullptr;
    cudaGetSymbolAddress(&pQp, g_Qp);
    cudaGetSymbolAddress(&pS,  g_S);
    float* Qp = (float*)pQp;
    float* S  = (float*)pS;

    const float inv_sqrt_d = 0.03125f;   // 1/sqrt(1024)

    // 1) Q projection: [16384,1024] = [16384,1024] @ [1024,1024]  (NN)
    {
        dim3 grid(DKEY_ / BN, (B_ * LQ_) / BM, 1);
        sgemm_kernel<false, false, false><<<grid, 256>>>(
            queries, Wq, Qp,
            B_ * LQ_, DKEY_, DQ_,
            0LL, 0LL, 0LL, 1.0f, nullptr);
    }

    // 2) Scores: S[b] = Qp[b] @ K[b]^T * (1/32)   (NT, skip masked N-tiles)
    {
        dim3 grid(LK_ / BN, LQ_ / BM, B_);
        sgemm_kernel<true, true, false><<<grid, 256>>>(
            Qp, keys, S,
            LQ_, LK_, DKEY_,
            (long long)LQ_ * DKEY_, (long long)LK_ * DKEY_, (long long)LQ_ * LK_,
            inv_sqrt_d, lens);
    }

    // 3) Masked softmax (writes exact zeros for s >= valid_len)
    softmax_mask_kernel<<<B_ * LQ_, 256>>>(S, lens);

    // 4) Output: out[b] = P[b] @ V[b]   (NN, K-loop clipped at valid_len)
    {
        dim3 grid(DV_ / BN, LQ_ / BM, B_);
        sgemm_kernel<false, false, true><<<grid, 256>>>(
            S, values, out,
            LQ_, DV_, LK_,
            (long long)LQ_ * LK_, (long long)LK_ * DV_, (long long)LQ_ * DV_,
            1.0f, lens);
    }
}

// round 2
// speedup vs baseline: 2.7581x; 2.7581x over previous
#include <cuda_runtime.h>
#include <cuda_bf16.h>

// ---------------------------------------------------------------------------
// Problem constants
// ---------------------------------------------------------------------------
#define B_   8
#define LQ_  2048
#define LK_  2048
#define DQ_  1024
#define DK_  1024
#define DV_  1024

constexpr size_t NQ  = (size_t)B_ * LQ_ * DQ_;    // 16.7M
constexpr size_t NKV = (size_t)B_ * LK_ * DK_;
constexpr size_t NS  = (size_t)B_ * LQ_ * LK_;
constexpr size_t NW  = (size_t)DK_ * DQ_;

// Scratch (__device__ globals: allocation-free rule)
__device__ __align__(256) __nv_bfloat16 g_Qhi[NQ],  g_Qlo[NQ];    // split queries
__device__ __align__(256) __nv_bfloat16 g_Khi[NKV], g_Klo[NKV];   // split keys [b][s][d]
__device__ __align__(256) __nv_bfloat16 g_Vthi[NKV], g_Vtlo[NKV]; // split values^T [b][v][s]
__device__ __align__(256) __nv_bfloat16 g_Wthi[NW], g_Wtlo[NW];   // split Wq^T [n][k]
__device__ __align__(256) __nv_bfloat16 g_Qphi[NQ], g_Qplo[NQ];   // split projected Q
__device__ __align__(256) float         g_S[NS];                  // scores
__device__ __align__(256) __nv_bfloat16 g_Phi[NS], g_Plo[NS];     // split softmax probs

// ---------------------------------------------------------------------------
// PTX helpers
// ---------------------------------------------------------------------------
__device__ __forceinline__ unsigned smem_u32(const void* p) {
    unsigned r;
    asm("{.reg .u64 t; cvta.to.shared.u64 t, %1; cvt.u32.u64 %0, t;}" : "=r"(r) : "l"(p));
    return r;
}
#define SWZ(b) ((b) ^ (((b) >> 3) & 0x30))

#define CPA(dst, src) \
    asm volatile("cp.async.cg.shared.global [%0], [%1], 16;\n" :: "r"(dst), "l"(src))
#define LDSM4(r0, r1, r2, r3, addr) \
    asm volatile("ldmatrix.sync.aligned.m8n8.x4.shared.b16 {%0,%1,%2,%3}, [%4];\n" \
                 : "=r"(r0), "=r"(r1), "=r"(r2), "=r"(r3) : "r"(addr))
#define MMA(d, a, bb) \
    asm volatile("mma.sync.aligned.m16n8k16.row.col.f32.bf16.bf16.f32 " \
                 "{%0,%1,%2,%3},{%4,%5,%6,%7},{%8,%9},{%0,%1,%2,%3};\n" \
                 : "+f"((d)[0]), "+f"((d)[1]), "+f"((d)[2]), "+f"((d)[3]) \
                 : "r"((a)[0]), "r"((a)[1]), "r"((a)[2]), "r"((a)[3]), \
                   "r"((bb)[0]), "r"((bb)[1]))

// ---------------------------------------------------------------------------
// 3-pass split-bf16 GEMM:  C = alpha * (Ahi+Alo) @ (Bhi+Blo)^T   (A:[M,K], B:[N,K])
// BM=BN=128, BK=32 (bf16), 256 threads, 8 warps (2x4), warp tile 64x32.
// cp.async double-buffered smem, SW64 swizzle, ldmatrix fragment loads.
// Passes: hi*hi + hi*lo + lo*hi  (lo*lo ~ 2^-18, dropped).
// SKIPN:  skip score N-tiles >= lens[b].   KBOUND: clip K to ceil(lens[b]/32)*32.
// SPLITOUT: write result as bf16 hi/lo arrays instead of fp32.
// ---------------------------------------------------------------------------
constexpr int BM = 128, BN = 128;
constexpr int STAGE  = 32768;     // bytes per pipeline stage (4 x 8KB tiles)
constexpr int OFF_AH = 0, OFF_AL = 8192, OFF_BH = 16384, OFF_BL = 24576;

template<bool SKIPN, bool KBOUND, bool SPLITOUT>
__global__ __launch_bounds__(256)
void mma_gemm(const __nv_bfloat16* __restrict__ Ahi, const __nv_bfloat16* __restrict__ Alo,
              const __nv_bfloat16* __restrict__ Bh,  const __nv_bfloat16* __restrict__ Bl,
              float* __restrict__ C,
              __nv_bfloat16* __restrict__ Chi, __nv_bfloat16* __restrict__ Clo,
              int N, int K,
              long long sA, long long sB, long long sC,
              float alpha, const int* __restrict__ lens)
{
    const int b = blockIdx.z;
    int L = 0;
    if (SKIPN || KBOUND) L = lens[b];
    if (SKIPN && (int)blockIdx.x * BN >= L) return;   // fully-masked score tile
    int Keff = K;
    if (KBOUND) { int r = (L + 31) & ~31; Keff = r < K ? r : K; }
    const int ntiles = Keff >> 5;

    extern __shared__ char smem[];
    const unsigned sb = smem_u32(smem);

    const int tid = threadIdx.x, lane = tid & 31, wid = tid >> 5;
    const int wm = wid >> 2, wn = wid & 3;           // warp grid 2(m) x 4(n)
    const long long m0 = (long long)blockIdx.y * BM;
    const long long n0 = (long long)blockIdx.x * BN;

    Ahi += (long long)b * sA;  Alo += (long long)b * sA;
    Bh  += (long long)b * sB;  Bl  += (long long)b * sB;

    // ---- staging: thread owns 2 (row, 16B-chunk) slots per 128x32 tile ----
    const int srow = tid >> 2, sch = tid & 3;
    const unsigned d0 = SWZ((unsigned)(srow * 64 + sch * 16));
    const unsigned d1 = SWZ((unsigned)((srow + 64) * 64 + sch * 16));
    const __nv_bfloat16* pAh0 = Ahi + (m0 + srow)      * (long long)K + sch * 8;
    const __nv_bfloat16* pAh1 = Ahi + (m0 + srow + 64) * (long long)K + sch * 8;
    const __nv_bfloat16* pAl0 = Alo + (m0 + srow)      * (long long)K + sch * 8;
    const __nv_bfloat16* pAl1 = Alo + (m0 + srow + 64) * (long long)K + sch * 8;
    const __nv_bfloat16* pBh0 = Bh  + (n0 + srow)      * (long long)K + sch * 8;
    const __nv_bfloat16* pBh1 = Bh  + (n0 + srow + 64) * (long long)K + sch * 8;
    const __nv_bfloat16* pBl0 = Bl  + (n0 + srow)      * (long long)K + sch * 8;
    const __nv_bfloat16* pBl1 = Bl  + (n0 + srow + 64) * (long long)K + sch * 8;

#define ISSUE(bufi, kt) do {                                               \
    unsigned s_ = sb + (unsigned)(bufi) * STAGE; int ko_ = (kt) * 32;      \
    CPA(s_ + OFF_AH + d0, pAh0 + ko_); CPA(s_ + OFF_AH + d1, pAh1 + ko_);  \
    CPA(s_ + OFF_AL + d0, pAl0 + ko_); CPA(s_ + OFF_AL + d1, pAl1 + ko_);  \
    CPA(s_ + OFF_BH + d0, pBh0 + ko_); CPA(s_ + OFF_BH + d1, pBh1 + ko_);  \
    CPA(s_ + OFF_BL + d0, pBl0 + ko_); CPA(s_ + OFF_BL + d1, pBl1 + ko_);  \
    asm volatile("cp.async.commit_group;\n" ::); } while (0)

    float acc[4][4][4];
#pragma unroll
    for (int i = 0; i < 4; i++)
#pragma unroll
        for (int j = 0; j < 4; j++)
#pragma unroll
            for (int k = 0; k < 4; k++) acc[i][j][k] = 0.f;

    ISSUE(0, 0);
    int buf = 0;

    // fragment address components
    const int arow = lane & 15;
    const int ak2  = ((lane >> 4) & 1) * 16;           // byte offset of k 8-col half
    const int g    = lane >> 3;                        // B ldmatrix group 0..3
    const int brow = ((g >> 1) << 3) + (lane & 7);
    const int bk2  = (g & 1) * 16;

    for (int kt = 0; kt < ntiles; kt++) {
        if (kt + 1 < ntiles) {
            ISSUE(buf ^ 1, kt + 1);
            asm volatile("cp.async.wait_group 1;\n" ::);
        } else {
            asm volatile("cp.async.wait_group 0;\n" ::);
        }
        __syncthreads();
        const unsigned base = sb + (unsigned)buf * STAGE;

#pragma unroll
        for (int ks = 0; ks < 2; ks++) {
            unsigned ah[4][4], al[4][4], bh[4][2], bl[4][2];
#pragma unroll
            for (int mi = 0; mi < 4; mi++) {
                int row = wm * 64 + mi * 16 + arow;
                unsigned sw = SWZ((unsigned)(row * 64 + ks * 32 + ak2));
                LDSM4(ah[mi][0], ah[mi][1], ah[mi][2], ah[mi][3], base + OFF_AH + sw);
                LDSM4(al[mi][0], al[mi][1], al[mi][2], al[mi][3], base + OFF_AL + sw);
            }
#pragma unroll
            for (int bi = 0; bi < 2; bi++) {
                int row = wn * 32 + bi * 16 + brow;
                unsigned sw = SWZ((unsigned)(row * 64 + ks * 32 + bk2));
                LDSM4(bh[2*bi][0], bh[2*bi][1], bh[2*bi+1][0], bh[2*bi+1][1], base + OFF_BH + sw);
                LDSM4(bl[2*bi][0], bl[2*bi][1], bl[2*bi+1][0], bl[2*bi+1][1], base + OFF_BL + sw);
            }
#pragma unroll
            for (int mi = 0; mi < 4; mi++)
#pragma unroll
                for (int ni = 0; ni < 4; ni++) MMA(acc[mi][ni], ah[mi], bh[ni]);
#pragma unroll
            for (int mi = 0; mi < 4; mi++)
#pragma unroll
                for (int ni = 0; ni < 4; ni++) MMA(acc[mi][ni], ah[mi], bl[ni]);
#pragma unroll
            for (int mi = 0; mi < 4; mi++)
#pragma unroll
                for (int ni = 0; ni < 4; ni++) MMA(acc[mi][ni], al[mi], bh[ni]);
        }
        __syncthreads();
        buf ^= 1;
    }
#undef ISSUE

    // ---- epilogue ----
    const int erow = lane >> 2, ecol = (lane & 3) << 1;
#pragma unroll
    for (int mi = 0; mi < 4; mi++) {
        long long r0 = m0 + wm * 64 + mi * 16 + erow;
#pragma unroll
        for (int ni = 0; ni < 4; ni++) {
            long long c0 = n0 + wn * 32 + ni * 8 + ecol;
            float v0 = acc[mi][ni][0] * alpha, v1 = acc[mi][ni][1] * alpha;
            float v2 = acc[mi][ni][2] * alpha, v3 = acc[mi][ni][3] * alpha;
            size_t i0 = (size_t)((long long)b * sC + r0 * N + c0);
            size_t i1 = i0 + (size_t)8 * N;
            if (SPLITOUT) {
                __nv_bfloat162 h0, l0, h1, l1;
                h0.x = __float2bfloat16(v0); l0.x = __float2bfloat16(v0 - __bfloat162float(h0.x));
                h0.y = __float2bfloat16(v1); l0.y = __float2bfloat16(v1 - __bfloat162float(h0.y));
                h1.x = __float2bfloat16(v2); l1.x = __float2bfloat16(v2 - __bfloat162float(h1.x));
                h1.y = __float2bfloat16(v3); l1.y = __float2bfloat16(v3 - __bfloat162float(h1.y));
                *(__nv_bfloat162*)&Chi[i0] = h0;  *(__nv_bfloat162*)&Clo[i0] = l0;
                *(__nv_bfloat162*)&Chi[i1] = h1;  *(__nv_bfloat162*)&Clo[i1] = l1;
            } else {
                float2 f0 = make_float2(v0, v1), f1 = make_float2(v2, v3);
                *(float2*)&C[i0] = f0;
                *(float2*)&C[i1] = f1;
            }
        }
    }
}

// ---------------------------------------------------------------------------
// Elementwise split: fp32 -> bf16 hi + bf16 lo (same layout)
// ---------------------------------------------------------------------------
__global__ __launch_bounds__(256)
void split_kernel(const float4* __restrict__ src, __nv_bfloat162* __restrict__ hi,
                  __nv_bfloat162* __restrict__ lo, size_t n4)
{
    size_t i = (size_t)blockIdx.x * blockDim.x + threadIdx.x;
    const size_t stride = (size_t)gridDim.x * blockDim.x;
    for (; i < n4; i += stride) {
        float4 v = src[i];
        __nv_bfloat162 h0, h1, l0, l1;
        h0.x = __float2bfloat16(v.x); l0.x = __float2bfloat16(v.x - __bfloat162float(h0.x));
        h0.y = __float2bfloat16(v.y); l0.y = __float2bfloat16(v.y - __bfloat162float(h0.y));
        h1.x = __float2bfloat16(v.z); l1.x = __float2bfloat16(v.z - __bfloat162float(h1.x));
        h1.y = __float2bfloat16(v.w); l1.y = __float2bfloat16(v.w - __bfloat162float(h1.y));
        hi[2*i] = h0; hi[2*i+1] = h1;
        lo[2*i] = l0; lo[2*i+1] = l1;
    }
}

// ---------------------------------------------------------------------------
// Transpose + split: src[b][r][c] fp32 -> hi/lo[b][c][r] bf16
// ---------------------------------------------------------------------------
__global__ __launch_bounds__(256)
void transpose_split(const float* __restrict__ src, __nv_bfloat16* __restrict__ hi,
                     __nv_bfloat16* __restrict__ lo, int rows, int cols)
{
    __shared__ float t[32][33];
    const int b = blockIdx.z;
    const size_t off = (size_t)b * rows * cols;
    const int c0 = blockIdx.x * 32, r0 = blockIdx.y * 32;
    const int tx = threadIdx.x, ty = threadIdx.y;   // 32 x 8
#pragma unroll
    for (int j = 0; j < 32; j += 8)
        t[ty + j][tx] = src[off + (size_t)(r0 + ty + j) * cols + c0 + tx];
    __syncthreads();
#pragma unroll
    for (int j = 0; j < 32; j += 8) {
        float v = t[tx][ty + j];
        __nv_bfloat16 h = __float2bfloat16(v);
        size_t o = off + (size_t)(c0 + ty + j) * rows + r0 + tx;
        hi[o] = h;
        lo[o] = __float2bfloat16(v - __bfloat162float(h));
    }
}

// ---------------------------------------------------------------------------
// Masked softmax over rows of S; writes split-bf16 P (exact zeros for s>=L).
// ---------------------------------------------------------------------------
__global__ __launch_bounds__(256)
void softmax_split(const float* __restrict__ S, __nv_bfloat16* __restrict__ Phi,
                   __nv_bfloat16* __restrict__ Plo, const int* __restrict__ lens)
{
    const int row = blockIdx.x;            // b*LQ + q
    const int b   = row / LQ_;
    const int L   = lens[b];
    const float* Sr = S + (size_t)row * LK_;
    __nv_bfloat16* Ph = Phi + (size_t)row * LK_;
    __nv_bfloat16* Pl = Plo + (size_t)row * LK_;

    const int tid = threadIdx.x;
    float v[8];
    float m = -3.4e38f;
#pragma unroll
    for (int i = 0; i < 8; i++) {
        const int s = tid + i * 256;
        v[i] = Sr[s];
        if (s < L) m = fmaxf(m, v[i]);
    }

    __shared__ float red[256];
    red[tid] = m;
    __syncthreads();
    for (int st = 128; st > 0; st >>= 1) {
        if (tid < st) red[tid] = fmaxf(red[tid], red[tid + st]);
        __syncthreads();
    }
    m = red[0];
    __syncthreads();

    float sum = 0.f;
#pragma unroll
    for (int i = 0; i < 8; i++) {
        const int s = tid + i * 256;
        v[i] = (s < L) ? expf(v[i] - m) : 0.f;
        sum += v[i];
    }
    red[tid] = sum;
    __syncthreads();
    for (int st = 128; st > 0; st >>= 1) {
        if (tid < st) red[tid] += red[tid + st];
        __syncthreads();
    }
    const float inv = 1.f / red[0];

#pragma unroll
    for (int i = 0; i < 8; i++) {
        const int s = tid + i * 256;
        float p = v[i] * inv;
        __nv_bfloat16 h = __float2bfloat16(p);
        Ph[s] = h;
        Pl[s] = __float2bfloat16(p - __bfloat162float(h));
    }
}

// ---------------------------------------------------------------------------
// Launch
// ---------------------------------------------------------------------------
extern "C" void kernel_launch(void* const* d_in, const int* in_sizes, int n_in,
                              void* d_out, int out_size)
{
    const float* queries = (const float*)d_in[0];   // [8,2048,1024]
    const float* keys    = (const float*)d_in[1];   // [8,2048,1024]
    const float* values  = (const float*)d_in[2];   // [8,2048,1024]
    const int*   lens    = (const int*)  d_in[3];   // [8]
    const float* Wq      = (const float*)d_in[4];   // [1024,1024]
    float*       out     = (float*)d_out;           // [8,2048,1024]

    void *pQhi, *pQlo, *pKhi, *pKlo, *pVthi, *pVtlo, *pWthi, *pWtlo;
    void *pQphi, *pQplo, *pS, *pPhi, *pPlo;
    cudaGetSymbolAddress(&pQhi,  g_Qhi);  cudaGetSymbolAddress(&pQlo,  g_Qlo);
    cudaGetSymbolAddress(&pKhi,  g_Khi);  cudaGetSymbolAddress(&pKlo,  g_Klo);
    cudaGetSymbolAddress(&pVthi, g_Vthi); cudaGetSymbolAddress(&pVtlo, g_Vtlo);
    cudaGetSymbolAddress(&pWthi, g_Wthi); cudaGetSymbolAddress(&pWtlo, g_Wtlo);
    cudaGetSymbolAddress(&pQphi, g_Qphi); cudaGetSymbolAddress(&pQplo, g_Qplo);
    cudaGetSymbolAddress(&pS,    g_S);
    cudaGetSymbolAddress(&pPhi,  g_Phi);  cudaGetSymbolAddress(&pPlo,  g_Plo);

    __nv_bfloat16 *Qhi = (__nv_bfloat16*)pQhi,  *Qlo = (__nv_bfloat16*)pQlo;
    __nv_bfloat16 *Khi = (__nv_bfloat16*)pKhi,  *Klo = (__nv_bfloat16*)pKlo;
    __nv_bfloat16 *Vthi = (__nv_bfloat16*)pVthi, *Vtlo = (__nv_bfloat16*)pVtlo;
    __nv_bfloat16 *Wthi = (__nv_bfloat16*)pWthi, *Wtlo = (__nv_bfloat16*)pWtlo;
    __nv_bfloat16 *Qphi = (__nv_bfloat16*)pQphi, *Qplo = (__nv_bfloat16*)pQplo;
    float *S = (float*)pS;
    __nv_bfloat16 *Phi = (__nv_bfloat16*)pPhi, *Plo = (__nv_bfloat16*)pPlo;

    const int smem = 2 * STAGE;   // 64 KB
    cudaFuncSetAttribute(mma_gemm<false, false, true >, cudaFuncAttributeMaxDynamicSharedMemorySize, smem);
    cudaFuncSetAttribute(mma_gemm<true,  false, false>, cudaFuncAttributeMaxDynamicSharedMemorySize, smem);
    cudaFuncSetAttribute(mma_gemm<false, true,  false>, cudaFuncAttributeMaxDynamicSharedMemorySize, smem);

    // 0) split / transpose-split prep
    split_kernel<<<2048, 256>>>((const float4*)queries, (__nv_bfloat162*)Qhi,
                                (__nv_bfloat162*)Qlo, NQ / 4);
    split_kernel<<<2048, 256>>>((const float4*)keys, (__nv_bfloat162*)Khi,
                                (__nv_bfloat162*)Klo, NKV / 4);
    transpose_split<<<dim3(DV_/32, LK_/32, B_), dim3(32, 8)>>>(values, Vthi, Vtlo, LK_, DV_);
    transpose_split<<<dim3(DK_/32, DQ_/32, 1), dim3(32, 8)>>>(Wq, Wthi, Wtlo, DQ_, DK_);

    // 1) Q projection -> split bf16 Qp   ([16384,1024] x [1024,1024]^T-form)
    mma_gemm<false, false, true><<<dim3(DK_/BN, (B_*LQ_)/BM, 1), 256, smem>>>(
        Qhi, Qlo, Wthi, Wtlo, nullptr, Qphi, Qplo,
        DK_, DQ_, 0LL, 0LL, 0LL, 1.0f, lens);

    // 2) Scores: S[b] = Qp[b] @ K[b]^T / 32   (skip masked N-tiles)
    mma_gemm<true, false, false><<<dim3(LK_/BN, LQ_/BM, B_), 256, smem>>>(
        Qphi, Qplo, Khi, Klo, S, nullptr, nullptr,
        LK_, DK_,
        (long long)LQ_ * DK_, (long long)LK_ * DK_, (long long)LQ_ * LK_,
        0.03125f, lens);

    // 3) Masked softmax -> split bf16 P
    softmax_split<<<B_ * LQ_, 256>>>(S, Phi, Plo, lens);

    // 4) out[b] = P[b] @ Vt[b]^T-form   (K clipped at valid_len)
    mma_gemm<false, true, false><<<dim3(DV_/BN, LQ_/BM, B_), 256, smem>>>(
        Phi, Plo, Vthi, Vtlo, out, nullptr, nullptr,
        DV_, LK_,
        (long long)LQ_ * LK_, (long long)DV_ * LK_, (long long)LQ_ * DV_,
        1.0f, lens);
}